// round 15
// baseline (speedup 1.0000x reference)
#include <cuda_runtime.h>

#define N_NODES_MAX 100000
#define N_GRAPHS    64
#define CAP         96          // ELL slots per node (indegree Poisson(32))
#define SPILL_MAX   8192

#define CDIV(a, b) (((a) + (b) - 1) / (b))

// ---------------------------------------------------------------------------
// Scratch (static device globals; no allocation allowed)
// ---------------------------------------------------------------------------
__device__ int    g_cur[N_NODES_MAX];           // fill cursor -> indegree
__device__ float  g_dinv[N_NODES_MAX];
__device__ int    g_ell[N_NODES_MAX * CAP];     // src ids grouped by dst
__device__ int2   g_spill[SPILL_MAX];           // (dst, src) overflow edges
__device__ int    g_spn;                        // spill count
__device__ float4 g_hs1[N_NODES_MAX * 4];       // layer1 feats (raw, then scaled)
__device__ float4 g_p2[N_NODES_MAX * 4];        // dinv-prescaled layer2 input
__device__ float  g_pool[N_GRAPHS * 32];
__device__ float  g_cnt[N_GRAPHS];

// ---------------------------------------------------------------------------
// 1) init: zero cursors, pool, cnt, spill counter (single kernel)
// ---------------------------------------------------------------------------
__global__ void k_init(int n) {
    int i = blockIdx.x * blockDim.x + threadIdx.x;
    if (i < n)             g_cur[i] = 0;
    if (i < N_GRAPHS * 32) g_pool[i] = 0.0f;
    if (i < N_GRAPHS)      g_cnt[i]  = 0.0f;
    if (i == 0)            g_spn = 0;
}

// ---------------------------------------------------------------------------
// place helper (ATOMG.ADD-return into per-dst cursor, ELL scatter store)
// ---------------------------------------------------------------------------
__device__ __forceinline__ void place_one(int d, int s) {
    int pos = atomicAdd(&g_cur[d], 1);
    if (pos < CAP) {
        g_ell[d * CAP + pos] = s;
    } else {
        int sp = atomicAdd(&g_spn, 1);
        if (sp < SPILL_MAX) g_spill[sp] = make_int2(d, s);
    }
}

__global__ void k_place_tail(const int* __restrict__ src,
                             const int* __restrict__ dst, int lo, int E) {
    int e = lo + blockIdx.x * blockDim.x + threadIdx.x;
    if (e >= E) return;
    place_one(__ldg(&dst[e]), __ldg(&src[e]));
}

__global__ void k_gemm1_only(const float*, const float*, int);  // fwd (fallback)

// ---------------------------------------------------------------------------
// 2) FUSED kernel (contiguous roles — R12 form, the 168.4us winner):
//    Blocks [0, gemmBlocks):      hs1_raw = x @ W1 (128 rows/block)
//    Blocks [gemmBlocks, total):  ELL placement, 4 edges/thread (int4)
// ---------------------------------------------------------------------------
__global__ __launch_bounds__(256) void k_fused(const float* __restrict__ x,
                                               const float* __restrict__ W1,
                                               const int4* __restrict__ src4,
                                               const int4* __restrict__ dst4,
                                               int E4, int n, int gemmBlocks) {
    __shared__ float4 xs[8 * 128];  // 16KB (gemm blocks only)
    __shared__ float4 Ws[512];      // 8KB

    int tid = threadIdx.x;

    if ((int)blockIdx.x >= gemmBlocks) {
        // ---- placement path ----
        int t = (blockIdx.x - gemmBlocks) * 256 + tid;
        if (t < E4) {
            int4 s = __ldg(&src4[t]);
            int4 d = __ldg(&dst4[t]);
            place_one(d.x, s.x);
            place_one(d.y, s.y);
            place_one(d.z, s.z);
            place_one(d.w, s.w);
        }
        return;
    }

    // ---- gemm path ----
    int base = blockIdx.x * 128;
    int rg = tid >> 2;   // 0..63 -> rows rg, rg+64
    int jg = tid & 3;    // output f4 0..3

    const float4* W4 = (const float4*)W1;
    Ws[tid]       = W4[tid];
    Ws[tid + 256] = W4[tid + 256];

    const float4* x4 = (const float4*)x;
    float4 acc[2];
    acc[0] = make_float4(0.f, 0.f, 0.f, 0.f);
    acc[1] = make_float4(0.f, 0.f, 0.f, 0.f);

    #pragma unroll
    for (int chunk = 0; chunk < 4; chunk++) {
        __syncthreads();
        #pragma unroll
        for (int m = 0; m < 4; m++) {
            int i   = m * 256 + tid;
            int row = i >> 3, c = i & 7;
            float4 v = make_float4(0.f, 0.f, 0.f, 0.f);
            if (base + row < n) v = x4[(size_t)(base + row) * 32 + chunk * 8 + c];
            xs[c * 128 + (row ^ c)] = v;
        }
        __syncthreads();

        #pragma unroll
        for (int c4 = 0; c4 < 8; c4++) {
            float4 xv0 = xs[c4 * 128 + (rg ^ c4)];
            float4 xv1 = xs[c4 * 128 + ((rg + 64) ^ c4)];
            #pragma unroll
            for (int kk = 0; kk < 4; kk++) {
                float4 w = Ws[(chunk * 32 + c4 * 4 + kk) * 4 + jg];
                float e0 = (kk == 0) ? xv0.x : (kk == 1) ? xv0.y
                         : (kk == 2) ? xv0.z : xv0.w;
                float e1 = (kk == 0) ? xv1.x : (kk == 1) ? xv1.y
                         : (kk == 2) ? xv1.z : xv1.w;
                acc[0].x = fmaf(e0, w.x, acc[0].x); acc[0].y = fmaf(e0, w.y, acc[0].y);
                acc[0].z = fmaf(e0, w.z, acc[0].z); acc[0].w = fmaf(e0, w.w, acc[0].w);
                acc[1].x = fmaf(e1, w.x, acc[1].x); acc[1].y = fmaf(e1, w.y, acc[1].y);
                acc[1].z = fmaf(e1, w.z, acc[1].z); acc[1].w = fmaf(e1, w.w, acc[1].w);
            }
        }
    }

    #pragma unroll
    for (int rr = 0; rr < 2; rr++) {
        int r = base + rr * 64 + rg;
        if (r < n) g_hs1[r * 4 + jg] = acc[rr];
    }
}

// Fallback standalone gemm (only used when int4 path is unavailable)
__global__ __launch_bounds__(256) void k_gemm1_only(const float* __restrict__ x,
                                                    const float* __restrict__ W1,
                                                    int n) {
    __shared__ float4 xs[8 * 128];
    __shared__ float4 Ws[512];
    int tid  = threadIdx.x;
    int base = blockIdx.x * 128;
    int rg = tid >> 2, jg = tid & 3;
    const float4* W4 = (const float4*)W1;
    Ws[tid] = W4[tid]; Ws[tid + 256] = W4[tid + 256];
    const float4* x4 = (const float4*)x;
    float4 acc[2];
    acc[0] = make_float4(0.f, 0.f, 0.f, 0.f);
    acc[1] = make_float4(0.f, 0.f, 0.f, 0.f);
    #pragma unroll
    for (int chunk = 0; chunk < 4; chunk++) {
        __syncthreads();
        #pragma unroll
        for (int m = 0; m < 4; m++) {
            int i = m * 256 + tid;
            int row = i >> 3, c = i & 7;
            float4 v = make_float4(0.f, 0.f, 0.f, 0.f);
            if (base + row < n) v = x4[(size_t)(base + row) * 32 + chunk * 8 + c];
            xs[c * 128 + (row ^ c)] = v;
        }
        __syncthreads();
        #pragma unroll
        for (int c4 = 0; c4 < 8; c4++) {
            float4 xv0 = xs[c4 * 128 + (rg ^ c4)];
            float4 xv1 = xs[c4 * 128 + ((rg + 64) ^ c4)];
            #pragma unroll
            for (int kk = 0; kk < 4; kk++) {
                float4 w = Ws[(chunk * 32 + c4 * 4 + kk) * 4 + jg];
                float e0 = (kk == 0) ? xv0.x : (kk == 1) ? xv0.y
                         : (kk == 2) ? xv0.z : xv0.w;
                float e1 = (kk == 0) ? xv1.x : (kk == 1) ? xv1.y
                         : (kk == 2) ? xv1.z : xv1.w;
                acc[0].x = fmaf(e0, w.x, acc[0].x); acc[0].y = fmaf(e0, w.y, acc[0].y);
                acc[0].z = fmaf(e0, w.z, acc[0].z); acc[0].w = fmaf(e0, w.w, acc[0].w);
                acc[1].x = fmaf(e1, w.x, acc[1].x); acc[1].y = fmaf(e1, w.y, acc[1].y);
                acc[1].z = fmaf(e1, w.z, acc[1].z); acc[1].w = fmaf(e1, w.w, acc[1].w);
            }
        }
    }
    #pragma unroll
    for (int rr = 0; rr < 2; rr++) {
        int r = base + rr * 64 + rg;
        if (r < n) g_hs1[r * 4 + jg] = acc[rr];
    }
}

// ---------------------------------------------------------------------------
// 3) scale (join point): dinv = rsqrt(indeg+1); hs1 *= dinv (in place)
// ---------------------------------------------------------------------------
__global__ void k_scale(int n) {
    int i = blockIdx.x * blockDim.x + threadIdx.x;
    if (i >= n * 4) return;
    int node = i >> 2;
    float din = rsqrtf((float)(g_cur[node] + 1));
    if ((i & 3) == 0) g_dinv[node] = din;
    float4 v = g_hs1[i];
    g_hs1[i] = make_float4(v.x * din, v.y * din, v.z * din, v.w * din);
}

// ---------------------------------------------------------------------------
// Warp-per-node aggregation core, idx-preload version.
//    One coalesced LDG loads 32 neighbor indices (lane l -> ell[base+jb+l];
//    always within the node's CAP=96 segment since jb<=64, l<=31).
//    4 rounds: shfl hands group grp its neighbor id; all 4 feature LDGs
//    are independent -> MLP 4 (was 2). Butterfly leaves every lane with
//    the chunk (lane&3) sum.
// ---------------------------------------------------------------------------
__device__ __forceinline__ float4 agg_warp(const float4* __restrict__ feat,
                                           int node, int lane) {
    int grp = lane >> 2;
    int c   = lane & 3;
    int cnt  = g_cur[node];
    int m    = min(cnt, CAP);
    int base = node * CAP;

    float4 a = make_float4(0.f, 0.f, 0.f, 0.f);

    for (int jb = 0; jb < m; jb += 32) {
        int idx = __ldg(&g_ell[base + jb + lane]);   // in-segment even if >= m
        int rem = m - jb;
        #pragma unroll
        for (int r = 0; r < 4; r++) {
            int s = __shfl_sync(0xffffffffu, idx, r * 8 + grp);
            if (r * 8 + grp < rem) {
                float4 v = __ldg(&feat[s * 4 + c]);
                a.x += v.x; a.y += v.y; a.z += v.z; a.w += v.w;
            }
        }
    }
    if (cnt > CAP && grp == 0) {   // rare overflow: lanes 0-3 scan spill list
        int spn = min(g_spn, SPILL_MAX);
        for (int k = 0; k < spn; k++) {
            int2 e = g_spill[k];
            if (e.x == node) {
                float4 v = feat[e.y * 4 + c];
                a.x += v.x; a.y += v.y; a.z += v.z; a.w += v.w;
            }
        }
    }

    #pragma unroll
    for (int off = 4; off < 32; off <<= 1) {
        a.x += __shfl_xor_sync(0xffffffffu, a.x, off);
        a.y += __shfl_xor_sync(0xffffffffu, a.y, off);
        a.z += __shfl_xor_sync(0xffffffffu, a.z, off);
        a.w += __shfl_xor_sync(0xffffffffu, a.w, off);
    }
    return a;   // all lanes: sum for chunk (lane & 3)
}

// 4) Layer-1 aggregation + epilogue: p2 = dinv * relu(dinv*(self+S) + b1)
__global__ __launch_bounds__(256) void k_agg1(const float* __restrict__ b1, int n) {
    int node = blockIdx.x * 8 + (threadIdx.x >> 5);
    if (node >= n) return;
    int lane = threadIdx.x & 31;

    float4 a = agg_warp(g_hs1, node, lane);

    if (lane < 4) {
        int c = lane;
        float4 self = g_hs1[node * 4 + c];
        a.x += self.x; a.y += self.y; a.z += self.z; a.w += self.w;
        float din = g_dinv[node];
        float4 bb = __ldg(&((const float4*)b1)[c]);
        float4 o;
        o.x = din * fmaxf(fmaf(din, a.x, bb.x), 0.f);
        o.y = din * fmaxf(fmaf(din, a.y, bb.y), 0.f);
        o.z = din * fmaxf(fmaf(din, a.z, bb.z), 0.f);
        o.w = din * fmaxf(fmaf(din, a.w, bb.w), 0.f);
        g_p2[node * 4 + c] = o;
    }
}

// ---------------------------------------------------------------------------
// 5) Fused layer-2 aggregation + GEMM (@W2 + b2 + relu) + global mean pool.
// ---------------------------------------------------------------------------
__global__ __launch_bounds__(256) void k_agg2pool(const int* __restrict__ batch,
                                                  const float* __restrict__ W2,
                                                  const float* __restrict__ b2,
                                                  int n) {
    __shared__ float W2s[512];
    __shared__ float sp[8][32];
    __shared__ int   sg[8];

    int tid  = threadIdx.x;
    int lane = tid & 31;
    int w    = tid >> 5;
    int node = blockIdx.x * 8 + w;

    #pragma unroll
    for (int i = tid; i < 512; i += 256) W2s[i] = W2[i];

    float out = 0.f;
    int gid = -1;

    if (node < n) {
        float4 a = agg_warp(g_p2, node, lane);
        float4 self = g_p2[node * 4 + (lane & 3)];
        a.x += self.x; a.y += self.y; a.z += self.z; a.w += self.w;
        float din = g_dinv[node];
        a.x *= din; a.y *= din; a.z *= din; a.w *= din;

        gid = __ldg(&batch[node]);
        __syncthreads();
        float acc = __ldg(&b2[lane]);
        #pragma unroll
        for (int k = 0; k < 16; k++) {
            float comp = ((k & 3) == 0) ? a.x : ((k & 3) == 1) ? a.y
                       : ((k & 3) == 2) ? a.z : a.w;
            float v = __shfl_sync(0xffffffffu, comp, k >> 2);
            acc = fmaf(v, W2s[k * 32 + lane], acc);
        }
        out = fmaxf(acc, 0.f);
    } else {
        __syncthreads();
    }

    sp[w][lane] = out;
    if (lane == 0) sg[w] = gid;
    __syncthreads();

    if (w == 0) {
        int cur = -1; float rs = 0.f, rc = 0.f;
        #pragma unroll
        for (int r = 0; r < 8; r++) {
            int g = sg[r];
            if (g < 0) continue;
            if (g != cur) {
                if (cur >= 0) {
                    atomicAdd(&g_pool[cur * 32 + lane], rs);
                    if (lane == 0) atomicAdd(&g_cnt[cur], rc);
                }
                cur = g; rs = 0.f; rc = 0.f;
            }
            rs += sp[r][lane];
            rc += 1.f;
        }
        if (cur >= 0) {
            atomicAdd(&g_pool[cur * 32 + lane], rs);
            if (lane == 0) atomicAdd(&g_cnt[cur], rc);
        }
    }
}

// ---------------------------------------------------------------------------
// 6) MLP head
// ---------------------------------------------------------------------------
__global__ __launch_bounds__(64) void k_mlp(const float* __restrict__ Wf1,
                                            const float* __restrict__ bf1,
                                            const float* __restrict__ Wf2,
                                            const float* __restrict__ bf2,
                                            float* __restrict__ out) {
    int g = threadIdx.x;
    if (g >= N_GRAPHS) return;

    float inv = 1.0f / fmaxf(g_cnt[g], 1.0f);
    float gv[32];
    #pragma unroll
    for (int c = 0; c < 32; c++) gv[c] = g_pool[g * 32 + c] * inv;

    float h[64];
    #pragma unroll 8
    for (int j = 0; j < 64; j++) {
        float s = __ldg(&bf1[j]);
        #pragma unroll
        for (int c = 0; c < 32; c++) s = fmaf(gv[c], __ldg(&Wf1[c * 64 + j]), s);
        h[j] = fmaxf(s, 0.f);
    }

    #pragma unroll
    for (int o = 0; o < 8; o++) {
        float s = __ldg(&bf2[o]);
        #pragma unroll 16
        for (int j = 0; j < 64; j++) s = fmaf(h[j], __ldg(&Wf2[j * 8 + o]), s);
        out[g * 8 + o] = s;
    }
}

// ---------------------------------------------------------------------------
// Launch: 6 kernels. k_agg1 at slot 4 -> profiled next round (verifies the
// idx-preload gather restructure).
// ---------------------------------------------------------------------------
extern "C" void kernel_launch(void* const* d_in, const int* in_sizes, int n_in,
                              void* d_out, int out_size) {
    const float* x     = (const float*)d_in[0];
    const int*   ei    = (const int*)  d_in[1];
    const int*   batch = (const int*)  d_in[2];
    const float* W1    = (const float*)d_in[3];
    const float* b1    = (const float*)d_in[4];
    const float* W2    = (const float*)d_in[5];
    const float* b2    = (const float*)d_in[6];
    const float* Wf1   = (const float*)d_in[7];
    const float* bf1   = (const float*)d_in[8];
    const float* Wf2   = (const float*)d_in[9];
    const float* bf2   = (const float*)d_in[10];
    float* out = (float*)d_out;

    int N = in_sizes[0] / 128;
    int E = in_sizes[1] / 2;
    const int* src = ei;
    const int* dst = ei + E;

    bool v4ok = ((E & 3) == 0) &&
                ((((unsigned long long)src) & 15ull) == 0) &&
                ((((unsigned long long)dst) & 15ull) == 0);
    int E4 = v4ok ? (E >> 2) : 0;

    int gemmBlocks = CDIV(N, 128);

    k_init<<<CDIV(N, 256), 256>>>(N);                               // 1
    if (v4ok) {
        int placeBlocks = CDIV(E4, 256);
        k_fused<<<gemmBlocks + placeBlocks, 256>>>(x, W1,
                (const int4*)src, (const int4*)dst, E4, N, gemmBlocks); // 2
    } else {
        k_gemm1_only<<<gemmBlocks, 256>>>(x, W1, N);
        k_place_tail<<<CDIV(E, 256), 256>>>(src, dst, 0, E);
    }
    k_scale<<<CDIV(N * 4, 256), 256>>>(N);                          // 3
    k_agg1 <<<CDIV(N, 8), 256>>>(b1, N);                            // 4 <- profiled
    k_agg2pool<<<CDIV(N, 8), 256>>>(batch, W2, b2, N);              // 5
    k_mlp  <<<1, 64>>>(Wf1, bf1, Wf2, bf2, out);                    // 6
}

// round 16
// speedup vs baseline: 1.0494x; 1.0494x over previous
#include <cuda_runtime.h>

#define N_NODES_MAX 100000
#define N_GRAPHS    64
#define CAP         96          // ELL slots per node (indegree Poisson(32))
#define SPILL_MAX   8192

#define CDIV(a, b) (((a) + (b) - 1) / (b))

// ---------------------------------------------------------------------------
// Scratch (static device globals; no allocation allowed)
// NOTE: ELL + spill store PRESCALED source ids (s*4 = float4-row offset),
// so gather addresses need only one add.
// ---------------------------------------------------------------------------
__device__ int    g_cur[N_NODES_MAX];           // fill cursor -> indegree
__device__ float  g_dinv[N_NODES_MAX];
__device__ int    g_ell[N_NODES_MAX * CAP];     // prescaled src ids by dst
__device__ int2   g_spill[SPILL_MAX];           // (dst, src*4) overflow edges
__device__ int    g_spn;                        // spill count
__device__ float4 g_hs1[N_NODES_MAX * 4];       // layer1 feats (raw, then scaled)
__device__ float4 g_p2[N_NODES_MAX * 4];        // dinv-prescaled layer2 input
__device__ float  g_pool[N_GRAPHS * 32];
__device__ float  g_cnt[N_GRAPHS];

// ---------------------------------------------------------------------------
// 1) init: zero cursors, pool, cnt, spill counter (single kernel)
// ---------------------------------------------------------------------------
__global__ void k_init(int n) {
    int i = blockIdx.x * blockDim.x + threadIdx.x;
    if (i < n)             g_cur[i] = 0;
    if (i < N_GRAPHS * 32) g_pool[i] = 0.0f;
    if (i < N_GRAPHS)      g_cnt[i]  = 0.0f;
    if (i == 0)            g_spn = 0;
}

// ---------------------------------------------------------------------------
// place helper: s4 is the PRESCALED source id (s*4)
// ---------------------------------------------------------------------------
__device__ __forceinline__ void place_one(int d, int s4) {
    int pos = atomicAdd(&g_cur[d], 1);
    if (pos < CAP) {
        g_ell[d * CAP + pos] = s4;
    } else {
        int sp = atomicAdd(&g_spn, 1);
        if (sp < SPILL_MAX) g_spill[sp] = make_int2(d, s4);
    }
}

__global__ void k_place_tail(const int* __restrict__ src,
                             const int* __restrict__ dst, int lo, int E) {
    int e = lo + blockIdx.x * blockDim.x + threadIdx.x;
    if (e >= E) return;
    place_one(__ldg(&dst[e]), __ldg(&src[e]) * 4);
}

__global__ void k_gemm1_only(const float*, const float*, int);  // fwd (fallback)

// ---------------------------------------------------------------------------
// 2) FUSED kernel (contiguous roles — R12 form):
//    Blocks [0, gemmBlocks):      hs1_raw = x @ W1 (128 rows/block)
//    Blocks [gemmBlocks, total):  ELL placement, 4 edges/thread (int4)
// ---------------------------------------------------------------------------
__global__ __launch_bounds__(256) void k_fused(const float* __restrict__ x,
                                               const float* __restrict__ W1,
                                               const int4* __restrict__ src4,
                                               const int4* __restrict__ dst4,
                                               int E4, int n, int gemmBlocks) {
    __shared__ float4 xs[8 * 128];  // 16KB (gemm blocks only)
    __shared__ float4 Ws[512];      // 8KB

    int tid = threadIdx.x;

    if ((int)blockIdx.x >= gemmBlocks) {
        // ---- placement path ----
        int t = (blockIdx.x - gemmBlocks) * 256 + tid;
        if (t < E4) {
            int4 s = __ldg(&src4[t]);
            int4 d = __ldg(&dst4[t]);
            place_one(d.x, s.x * 4);
            place_one(d.y, s.y * 4);
            place_one(d.z, s.z * 4);
            place_one(d.w, s.w * 4);
        }
        return;
    }

    // ---- gemm path ----
    int base = blockIdx.x * 128;
    int rg = tid >> 2;   // 0..63 -> rows rg, rg+64
    int jg = tid & 3;    // output f4 0..3

    const float4* W4 = (const float4*)W1;
    Ws[tid]       = W4[tid];
    Ws[tid + 256] = W4[tid + 256];

    const float4* x4 = (const float4*)x;
    float4 acc[2];
    acc[0] = make_float4(0.f, 0.f, 0.f, 0.f);
    acc[1] = make_float4(0.f, 0.f, 0.f, 0.f);

    #pragma unroll
    for (int chunk = 0; chunk < 4; chunk++) {
        __syncthreads();
        #pragma unroll
        for (int m = 0; m < 4; m++) {
            int i   = m * 256 + tid;
            int row = i >> 3, c = i & 7;
            float4 v = make_float4(0.f, 0.f, 0.f, 0.f);
            if (base + row < n) v = x4[(size_t)(base + row) * 32 + chunk * 8 + c];
            xs[c * 128 + (row ^ c)] = v;
        }
        __syncthreads();

        #pragma unroll
        for (int c4 = 0; c4 < 8; c4++) {
            float4 xv0 = xs[c4 * 128 + (rg ^ c4)];
            float4 xv1 = xs[c4 * 128 + ((rg + 64) ^ c4)];
            #pragma unroll
            for (int kk = 0; kk < 4; kk++) {
                float4 w = Ws[(chunk * 32 + c4 * 4 + kk) * 4 + jg];
                float e0 = (kk == 0) ? xv0.x : (kk == 1) ? xv0.y
                         : (kk == 2) ? xv0.z : xv0.w;
                float e1 = (kk == 0) ? xv1.x : (kk == 1) ? xv1.y
                         : (kk == 2) ? xv1.z : xv1.w;
                acc[0].x = fmaf(e0, w.x, acc[0].x); acc[0].y = fmaf(e0, w.y, acc[0].y);
                acc[0].z = fmaf(e0, w.z, acc[0].z); acc[0].w = fmaf(e0, w.w, acc[0].w);
                acc[1].x = fmaf(e1, w.x, acc[1].x); acc[1].y = fmaf(e1, w.y, acc[1].y);
                acc[1].z = fmaf(e1, w.z, acc[1].z); acc[1].w = fmaf(e1, w.w, acc[1].w);
            }
        }
    }

    #pragma unroll
    for (int rr = 0; rr < 2; rr++) {
        int r = base + rr * 64 + rg;
        if (r < n) g_hs1[r * 4 + jg] = acc[rr];
    }
}

// Fallback standalone gemm (only used when int4 path is unavailable)
__global__ __launch_bounds__(256) void k_gemm1_only(const float* __restrict__ x,
                                                    const float* __restrict__ W1,
                                                    int n) {
    __shared__ float4 xs[8 * 128];
    __shared__ float4 Ws[512];
    int tid  = threadIdx.x;
    int base = blockIdx.x * 128;
    int rg = tid >> 2, jg = tid & 3;
    const float4* W4 = (const float4*)W1;
    Ws[tid] = W4[tid]; Ws[tid + 256] = W4[tid + 256];
    const float4* x4 = (const float4*)x;
    float4 acc[2];
    acc[0] = make_float4(0.f, 0.f, 0.f, 0.f);
    acc[1] = make_float4(0.f, 0.f, 0.f, 0.f);
    #pragma unroll
    for (int chunk = 0; chunk < 4; chunk++) {
        __syncthreads();
        #pragma unroll
        for (int m = 0; m < 4; m++) {
            int i = m * 256 + tid;
            int row = i >> 3, c = i & 7;
            float4 v = make_float4(0.f, 0.f, 0.f, 0.f);
            if (base + row < n) v = x4[(size_t)(base + row) * 32 + chunk * 8 + c];
            xs[c * 128 + (row ^ c)] = v;
        }
        __syncthreads();
        #pragma unroll
        for (int c4 = 0; c4 < 8; c4++) {
            float4 xv0 = xs[c4 * 128 + (rg ^ c4)];
            float4 xv1 = xs[c4 * 128 + ((rg + 64) ^ c4)];
            #pragma unroll
            for (int kk = 0; kk < 4; kk++) {
                float4 w = Ws[(chunk * 32 + c4 * 4 + kk) * 4 + jg];
                float e0 = (kk == 0) ? xv0.x : (kk == 1) ? xv0.y
                         : (kk == 2) ? xv0.z : xv0.w;
                float e1 = (kk == 0) ? xv1.x : (kk == 1) ? xv1.y
                         : (kk == 2) ? xv1.z : xv1.w;
                acc[0].x = fmaf(e0, w.x, acc[0].x); acc[0].y = fmaf(e0, w.y, acc[0].y);
                acc[0].z = fmaf(e0, w.z, acc[0].z); acc[0].w = fmaf(e0, w.w, acc[0].w);
                acc[1].x = fmaf(e1, w.x, acc[1].x); acc[1].y = fmaf(e1, w.y, acc[1].y);
                acc[1].z = fmaf(e1, w.z, acc[1].z); acc[1].w = fmaf(e1, w.w, acc[1].w);
            }
        }
    }
    #pragma unroll
    for (int rr = 0; rr < 2; rr++) {
        int r = base + rr * 64 + rg;
        if (r < n) g_hs1[r * 4 + jg] = acc[rr];
    }
}

// ---------------------------------------------------------------------------
// 3) scale (join point): dinv = rsqrt(indeg+1); hs1 *= dinv (in place)
// ---------------------------------------------------------------------------
__global__ void k_scale(int n) {
    int i = blockIdx.x * blockDim.x + threadIdx.x;
    if (i >= n * 4) return;
    int node = i >> 2;
    float din = rsqrtf((float)(g_cur[node] + 1));
    if ((i & 3) == 0) g_dinv[node] = din;
    float4 v = g_hs1[i];
    g_hs1[i] = make_float4(v.x * din, v.y * din, v.z * din, v.w * din);
}

// ---------------------------------------------------------------------------
// Warp-per-node aggregation core (R12 form, prescaled indices).
//    Lane l = (neighbor group l>>2, feature chunk l&3). Per round the warp
//    gathers 8 neighbors x 16B, unroll 2 -> 16/iter, then an 8-wide tail.
//    ELL holds s*4 -> gather address is a single add.
//    shfl_xor(4/8/16) butterfly: EVERY lane ends with the sum for chunk l&3.
// ---------------------------------------------------------------------------
__device__ __forceinline__ float4 agg_warp(const float4* __restrict__ feat,
                                           int node, int lane) {
    int grp = lane >> 2;
    int c   = lane & 3;
    int cnt  = g_cur[node];
    int m    = min(cnt, CAP);
    int base = node * CAP;

    float4 a = make_float4(0.f, 0.f, 0.f, 0.f);

    int j = 0;
    for (; j + 16 <= m; j += 16) {
        int s0 = __ldg(&g_ell[base + j + grp]);        // prescaled (s*4)
        int s1 = __ldg(&g_ell[base + j + 8 + grp]);
        float4 v0 = __ldg(&feat[s0 + c]);
        float4 v1 = __ldg(&feat[s1 + c]);
        a.x += v0.x + v1.x; a.y += v0.y + v1.y;
        a.z += v0.z + v1.z; a.w += v0.w + v1.w;
    }
    for (; j < m; j += 8) {
        int jj = j + grp;
        if (jj < m) {
            int s = __ldg(&g_ell[base + jj]);
            float4 v = __ldg(&feat[s + c]);
            a.x += v.x; a.y += v.y; a.z += v.z; a.w += v.w;
        }
    }
    if (cnt > CAP && grp == 0) {   // rare overflow: lanes 0-3 scan spill list
        int spn = min(g_spn, SPILL_MAX);
        for (int k = 0; k < spn; k++) {
            int2 e = g_spill[k];
            if (e.x == node) {
                float4 v = feat[e.y + c];              // e.y prescaled
                a.x += v.x; a.y += v.y; a.z += v.z; a.w += v.w;
            }
        }
    }

    #pragma unroll
    for (int off = 4; off < 32; off <<= 1) {
        a.x += __shfl_xor_sync(0xffffffffu, a.x, off);
        a.y += __shfl_xor_sync(0xffffffffu, a.y, off);
        a.z += __shfl_xor_sync(0xffffffffu, a.z, off);
        a.w += __shfl_xor_sync(0xffffffffu, a.w, off);
    }
    return a;   // all lanes: sum for chunk (lane & 3)
}

// 4) Layer-1 aggregation + epilogue: p2 = dinv * relu(dinv*(self+S) + b1)
__global__ __launch_bounds__(256) void k_agg1(const float* __restrict__ b1, int n) {
    int node = blockIdx.x * 8 + (threadIdx.x >> 5);
    if (node >= n) return;
    int lane = threadIdx.x & 31;

    float4 a = agg_warp(g_hs1, node, lane);

    if (lane < 4) {
        int c = lane;
        float4 self = g_hs1[node * 4 + c];
        a.x += self.x; a.y += self.y; a.z += self.z; a.w += self.w;
        float din = g_dinv[node];
        float4 bb = __ldg(&((const float4*)b1)[c]);
        float4 o;
        o.x = din * fmaxf(fmaf(din, a.x, bb.x), 0.f);
        o.y = din * fmaxf(fmaf(din, a.y, bb.y), 0.f);
        o.z = din * fmaxf(fmaf(din, a.z, bb.z), 0.f);
        o.w = din * fmaxf(fmaf(din, a.w, bb.w), 0.f);
        g_p2[node * 4 + c] = o;
    }
}

// ---------------------------------------------------------------------------
// 5) Fused layer-2 aggregation + GEMM (@W2 + b2 + relu) + global mean pool.
// ---------------------------------------------------------------------------
__global__ __launch_bounds__(256) void k_agg2pool(const int* __restrict__ batch,
                                                  const float* __restrict__ W2,
                                                  const float* __restrict__ b2,
                                                  int n) {
    __shared__ float W2s[512];
    __shared__ float sp[8][32];
    __shared__ int   sg[8];

    int tid  = threadIdx.x;
    int lane = tid & 31;
    int w    = tid >> 5;
    int node = blockIdx.x * 8 + w;

    #pragma unroll
    for (int i = tid; i < 512; i += 256) W2s[i] = W2[i];

    float out = 0.f;
    int gid = -1;

    if (node < n) {
        float4 a = agg_warp(g_p2, node, lane);
        float4 self = g_p2[node * 4 + (lane & 3)];
        a.x += self.x; a.y += self.y; a.z += self.z; a.w += self.w;
        float din = g_dinv[node];
        a.x *= din; a.y *= din; a.z *= din; a.w *= din;

        gid = __ldg(&batch[node]);
        __syncthreads();
        float acc = __ldg(&b2[lane]);
        #pragma unroll
        for (int k = 0; k < 16; k++) {
            float comp = ((k & 3) == 0) ? a.x : ((k & 3) == 1) ? a.y
                       : ((k & 3) == 2) ? a.z : a.w;
            float v = __shfl_sync(0xffffffffu, comp, k >> 2);
            acc = fmaf(v, W2s[k * 32 + lane], acc);
        }
        out = fmaxf(acc, 0.f);
    } else {
        __syncthreads();
    }

    sp[w][lane] = out;
    if (lane == 0) sg[w] = gid;
    __syncthreads();

    if (w == 0) {
        int cur = -1; float rs = 0.f, rc = 0.f;
        #pragma unroll
        for (int r = 0; r < 8; r++) {
            int g = sg[r];
            if (g < 0) continue;
            if (g != cur) {
                if (cur >= 0) {
                    atomicAdd(&g_pool[cur * 32 + lane], rs);
                    if (lane == 0) atomicAdd(&g_cnt[cur], rc);
                }
                cur = g; rs = 0.f; rc = 0.f;
            }
            rs += sp[r][lane];
            rc += 1.f;
        }
        if (cur >= 0) {
            atomicAdd(&g_pool[cur * 32 + lane], rs);
            if (lane == 0) atomicAdd(&g_cnt[cur], rc);
        }
    }
}

// ---------------------------------------------------------------------------
// 6) MLP head
// ---------------------------------------------------------------------------
__global__ __launch_bounds__(64) void k_mlp(const float* __restrict__ Wf1,
                                            const float* __restrict__ bf1,
                                            const float* __restrict__ Wf2,
                                            const float* __restrict__ bf2,
                                            float* __restrict__ out) {
    int g = threadIdx.x;
    if (g >= N_GRAPHS) return;

    float inv = 1.0f / fmaxf(g_cnt[g], 1.0f);
    float gv[32];
    #pragma unroll
    for (int c = 0; c < 32; c++) gv[c] = g_pool[g * 32 + c] * inv;

    float h[64];
    #pragma unroll 8
    for (int j = 0; j < 64; j++) {
        float s = __ldg(&bf1[j]);
        #pragma unroll
        for (int c = 0; c < 32; c++) s = fmaf(gv[c], __ldg(&Wf1[c * 64 + j]), s);
        h[j] = fmaxf(s, 0.f);
    }

    #pragma unroll
    for (int o = 0; o < 8; o++) {
        float s = __ldg(&bf2[o]);
        #pragma unroll 16
        for (int j = 0; j < 64; j++) s = fmaf(h[j], __ldg(&Wf2[j * 8 + o]), s);
        out[g * 8 + o] = s;
    }
}

// ---------------------------------------------------------------------------
// Launch: 6 kernels. k_agg1 at slot 4 -> clean A/B vs R12 (prescaled idx).
// ---------------------------------------------------------------------------
extern "C" void kernel_launch(void* const* d_in, const int* in_sizes, int n_in,
                              void* d_out, int out_size) {
    const float* x     = (const float*)d_in[0];
    const int*   ei    = (const int*)  d_in[1];
    const int*   batch = (const int*)  d_in[2];
    const float* W1    = (const float*)d_in[3];
    const float* b1    = (const float*)d_in[4];
    const float* W2    = (const float*)d_in[5];
    const float* b2    = (const float*)d_in[6];
    const float* Wf1   = (const float*)d_in[7];
    const float* bf1   = (const float*)d_in[8];
    const float* Wf2   = (const float*)d_in[9];
    const float* bf2   = (const float*)d_in[10];
    float* out = (float*)d_out;

    int N = in_sizes[0] / 128;
    int E = in_sizes[1] / 2;
    const int* src = ei;
    const int* dst = ei + E;

    bool v4ok = ((E & 3) == 0) &&
                ((((unsigned long long)src) & 15ull) == 0) &&
                ((((unsigned long long)dst) & 15ull) == 0);
    int E4 = v4ok ? (E >> 2) : 0;

    int gemmBlocks = CDIV(N, 128);

    k_init<<<CDIV(N, 256), 256>>>(N);                               // 1
    if (v4ok) {
        int placeBlocks = CDIV(E4, 256);
        k_fused<<<gemmBlocks + placeBlocks, 256>>>(x, W1,
                (const int4*)src, (const int4*)dst, E4, N, gemmBlocks); // 2
    } else {
        k_gemm1_only<<<gemmBlocks, 256>>>(x, W1, N);
        k_place_tail<<<CDIV(E, 256), 256>>>(src, dst, 0, E);
    }
    k_scale<<<CDIV(N * 4, 256), 256>>>(N);                          // 3
    k_agg1 <<<CDIV(N, 8), 256>>>(b1, N);                            // 4 <- profiled
    k_agg2pool<<<CDIV(N, 8), 256>>>(batch, W2, b2, N);              // 5
    k_mlp  <<<1, 64>>>(Wf1, bf1, Wf2, bf2, out);                    // 6
}

// round 17
// speedup vs baseline: 1.0639x; 1.0138x over previous
#include <cuda_runtime.h>

#define N_NODES_MAX 100000
#define N_GRAPHS    64
#define CAP         96          // ELL slots per node (indegree Poisson(32))
#define SPILL_MAX   8192

#define CDIV(a, b) (((a) + (b) - 1) / (b))

// ---------------------------------------------------------------------------
// Scratch (static device globals; zero-initialized at module load).
// SELF-CLEANING: every consumer restores zeros for the next graph replay,
// so no init kernel is needed.
// ELL + spill store PRESCALED source ids (s*4 = float4-row offset).
// ---------------------------------------------------------------------------
__device__ int    g_cur[N_NODES_MAX];           // fill cursor -> indegree
__device__ float  g_dinv[N_NODES_MAX];
__device__ int    g_ell[N_NODES_MAX * CAP];     // prescaled src ids by dst
__device__ int2   g_spill[SPILL_MAX];           // (dst, src*4) overflow edges
__device__ int    g_spn;                        // spill count
__device__ float4 g_hs1[N_NODES_MAX * 4];       // layer1 feats (raw, then scaled)
__device__ float4 g_p2[N_NODES_MAX * 4];        // dinv-prescaled layer2 input
__device__ float  g_pool[N_GRAPHS * 32];
__device__ float  g_cnt[N_GRAPHS];

// ---------------------------------------------------------------------------
// place helper: s4 is the PRESCALED source id (s*4)
// ---------------------------------------------------------------------------
__device__ __forceinline__ void place_one(int d, int s4) {
    int pos = atomicAdd(&g_cur[d], 1);
    if (pos < CAP) {
        g_ell[d * CAP + pos] = s4;
    } else {
        int sp = atomicAdd(&g_spn, 1);
        if (sp < SPILL_MAX) g_spill[sp] = make_int2(d, s4);
    }
}

__global__ void k_place_tail(const int* __restrict__ src,
                             const int* __restrict__ dst, int lo, int E) {
    int e = lo + blockIdx.x * blockDim.x + threadIdx.x;
    if (e >= E) return;
    place_one(__ldg(&dst[e]), __ldg(&src[e]) * 4);
}

__global__ void k_gemm1_only(const float*, const float*, int);  // fwd (fallback)

// ---------------------------------------------------------------------------
// 1) FUSED kernel (contiguous roles):
//    Blocks [0, gemmBlocks):      hs1_raw = x @ W1 (128 rows/block)
//    Blocks [gemmBlocks, total):  ELL placement, 4 edges/thread (int4)
// ---------------------------------------------------------------------------
__global__ __launch_bounds__(256) void k_fused(const float* __restrict__ x,
                                               const float* __restrict__ W1,
                                               const int4* __restrict__ src4,
                                               const int4* __restrict__ dst4,
                                               int E4, int n, int gemmBlocks) {
    __shared__ float4 xs[8 * 128];  // 16KB (gemm blocks only)
    __shared__ float4 Ws[512];      // 8KB

    int tid = threadIdx.x;

    if ((int)blockIdx.x >= gemmBlocks) {
        // ---- placement path ----
        int t = (blockIdx.x - gemmBlocks) * 256 + tid;
        if (t < E4) {
            int4 s = __ldg(&src4[t]);
            int4 d = __ldg(&dst4[t]);
            place_one(d.x, s.x * 4);
            place_one(d.y, s.y * 4);
            place_one(d.z, s.z * 4);
            place_one(d.w, s.w * 4);
        }
        return;
    }

    // ---- gemm path ----
    int base = blockIdx.x * 128;
    int rg = tid >> 2;   // 0..63 -> rows rg, rg+64
    int jg = tid & 3;    // output f4 0..3

    const float4* W4 = (const float4*)W1;
    Ws[tid]       = W4[tid];
    Ws[tid + 256] = W4[tid + 256];

    const float4* x4 = (const float4*)x;
    float4 acc[2];
    acc[0] = make_float4(0.f, 0.f, 0.f, 0.f);
    acc[1] = make_float4(0.f, 0.f, 0.f, 0.f);

    #pragma unroll
    for (int chunk = 0; chunk < 4; chunk++) {
        __syncthreads();
        #pragma unroll
        for (int m = 0; m < 4; m++) {
            int i   = m * 256 + tid;
            int row = i >> 3, c = i & 7;
            float4 v = make_float4(0.f, 0.f, 0.f, 0.f);
            if (base + row < n) v = x4[(size_t)(base + row) * 32 + chunk * 8 + c];
            xs[c * 128 + (row ^ c)] = v;
        }
        __syncthreads();

        #pragma unroll
        for (int c4 = 0; c4 < 8; c4++) {
            float4 xv0 = xs[c4 * 128 + (rg ^ c4)];
            float4 xv1 = xs[c4 * 128 + ((rg + 64) ^ c4)];
            #pragma unroll
            for (int kk = 0; kk < 4; kk++) {
                float4 w = Ws[(chunk * 32 + c4 * 4 + kk) * 4 + jg];
                float e0 = (kk == 0) ? xv0.x : (kk == 1) ? xv0.y
                         : (kk == 2) ? xv0.z : xv0.w;
                float e1 = (kk == 0) ? xv1.x : (kk == 1) ? xv1.y
                         : (kk == 2) ? xv1.z : xv1.w;
                acc[0].x = fmaf(e0, w.x, acc[0].x); acc[0].y = fmaf(e0, w.y, acc[0].y);
                acc[0].z = fmaf(e0, w.z, acc[0].z); acc[0].w = fmaf(e0, w.w, acc[0].w);
                acc[1].x = fmaf(e1, w.x, acc[1].x); acc[1].y = fmaf(e1, w.y, acc[1].y);
                acc[1].z = fmaf(e1, w.z, acc[1].z); acc[1].w = fmaf(e1, w.w, acc[1].w);
            }
        }
    }

    #pragma unroll
    for (int rr = 0; rr < 2; rr++) {
        int r = base + rr * 64 + rg;
        if (r < n) g_hs1[r * 4 + jg] = acc[rr];
    }
}

// Fallback standalone gemm (only used when int4 path is unavailable)
__global__ __launch_bounds__(256) void k_gemm1_only(const float* __restrict__ x,
                                                    const float* __restrict__ W1,
                                                    int n) {
    __shared__ float4 xs[8 * 128];
    __shared__ float4 Ws[512];
    int tid  = threadIdx.x;
    int base = blockIdx.x * 128;
    int rg = tid >> 2, jg = tid & 3;
    const float4* W4 = (const float4*)W1;
    Ws[tid] = W4[tid]; Ws[tid + 256] = W4[tid + 256];
    const float4* x4 = (const float4*)x;
    float4 acc[2];
    acc[0] = make_float4(0.f, 0.f, 0.f, 0.f);
    acc[1] = make_float4(0.f, 0.f, 0.f, 0.f);
    #pragma unroll
    for (int chunk = 0; chunk < 4; chunk++) {
        __syncthreads();
        #pragma unroll
        for (int m = 0; m < 4; m++) {
            int i = m * 256 + tid;
            int row = i >> 3, c = i & 7;
            float4 v = make_float4(0.f, 0.f, 0.f, 0.f);
            if (base + row < n) v = x4[(size_t)(base + row) * 32 + chunk * 8 + c];
            xs[c * 128 + (row ^ c)] = v;
        }
        __syncthreads();
        #pragma unroll
        for (int c4 = 0; c4 < 8; c4++) {
            float4 xv0 = xs[c4 * 128 + (rg ^ c4)];
            float4 xv1 = xs[c4 * 128 + ((rg + 64) ^ c4)];
            #pragma unroll
            for (int kk = 0; kk < 4; kk++) {
                float4 w = Ws[(chunk * 32 + c4 * 4 + kk) * 4 + jg];
                float e0 = (kk == 0) ? xv0.x : (kk == 1) ? xv0.y
                         : (kk == 2) ? xv0.z : xv0.w;
                float e1 = (kk == 0) ? xv1.x : (kk == 1) ? xv1.y
                         : (kk == 2) ? xv1.z : xv1.w;
                acc[0].x = fmaf(e0, w.x, acc[0].x); acc[0].y = fmaf(e0, w.y, acc[0].y);
                acc[0].z = fmaf(e0, w.z, acc[0].z); acc[0].w = fmaf(e0, w.w, acc[0].w);
                acc[1].x = fmaf(e1, w.x, acc[1].x); acc[1].y = fmaf(e1, w.y, acc[1].y);
                acc[1].z = fmaf(e1, w.z, acc[1].z); acc[1].w = fmaf(e1, w.w, acc[1].w);
            }
        }
    }
    #pragma unroll
    for (int rr = 0; rr < 2; rr++) {
        int r = base + rr * 64 + rg;
        if (r < n) g_hs1[r * 4 + jg] = acc[rr];
    }
}

// ---------------------------------------------------------------------------
// 2) scale (join point): dinv = rsqrt(indeg+1); hs1 *= dinv (in place)
// ---------------------------------------------------------------------------
__global__ void k_scale(int n) {
    int i = blockIdx.x * blockDim.x + threadIdx.x;
    if (i >= n * 4) return;
    int node = i >> 2;
    float din = rsqrtf((float)(g_cur[node] + 1));
    if ((i & 3) == 0) g_dinv[node] = din;
    float4 v = g_hs1[i];
    g_hs1[i] = make_float4(v.x * din, v.y * din, v.z * din, v.w * din);
}

// ---------------------------------------------------------------------------
// Warp-per-node aggregation core (prescaled indices).
//    Lane l = (neighbor group l>>2, feature chunk l&3). Per round the warp
//    gathers 8 neighbors x 16B, unroll 2 -> 16/iter, then an 8-wide tail.
//    shfl_xor(4/8/16) butterfly: EVERY lane ends with the sum for chunk l&3.
// ---------------------------------------------------------------------------
__device__ __forceinline__ float4 agg_warp(const float4* __restrict__ feat,
                                           int node, int lane, int cnt) {
    int grp = lane >> 2;
    int c   = lane & 3;
    int m    = min(cnt, CAP);
    int base = node * CAP;

    float4 a = make_float4(0.f, 0.f, 0.f, 0.f);

    int j = 0;
    for (; j + 16 <= m; j += 16) {
        int s0 = __ldg(&g_ell[base + j + grp]);        // prescaled (s*4)
        int s1 = __ldg(&g_ell[base + j + 8 + grp]);
        float4 v0 = __ldg(&feat[s0 + c]);
        float4 v1 = __ldg(&feat[s1 + c]);
        a.x += v0.x + v1.x; a.y += v0.y + v1.y;
        a.z += v0.z + v1.z; a.w += v0.w + v1.w;
    }
    for (; j < m; j += 8) {
        int jj = j + grp;
        if (jj < m) {
            int s = __ldg(&g_ell[base + jj]);
            float4 v = __ldg(&feat[s + c]);
            a.x += v.x; a.y += v.y; a.z += v.z; a.w += v.w;
        }
    }
    if (cnt > CAP && grp == 0) {   // rare overflow: lanes 0-3 scan spill list
        int spn = min(g_spn, SPILL_MAX);
        for (int k = 0; k < spn; k++) {
            int2 e = g_spill[k];
            if (e.x == node) {
                float4 v = feat[e.y + c];              // e.y prescaled
                a.x += v.x; a.y += v.y; a.z += v.z; a.w += v.w;
            }
        }
    }

    #pragma unroll
    for (int off = 4; off < 32; off <<= 1) {
        a.x += __shfl_xor_sync(0xffffffffu, a.x, off);
        a.y += __shfl_xor_sync(0xffffffffu, a.y, off);
        a.z += __shfl_xor_sync(0xffffffffu, a.z, off);
        a.w += __shfl_xor_sync(0xffffffffu, a.w, off);
    }
    return a;   // all lanes: sum for chunk (lane & 3)
}

// 3) Layer-1 aggregation + epilogue: p2 = dinv * relu(dinv*(self+S) + b1)
__global__ __launch_bounds__(256) void k_agg1(const float* __restrict__ b1, int n) {
    int node = blockIdx.x * 8 + (threadIdx.x >> 5);
    if (node >= n) return;
    int lane = threadIdx.x & 31;

    int cnt = g_cur[node];
    float4 a = agg_warp(g_hs1, node, lane, cnt);

    if (lane < 4) {
        int c = lane;
        float4 self = g_hs1[node * 4 + c];
        a.x += self.x; a.y += self.y; a.z += self.z; a.w += self.w;
        float din = g_dinv[node];
        float4 bb = __ldg(&((const float4*)b1)[c]);
        float4 o;
        o.x = din * fmaxf(fmaf(din, a.x, bb.x), 0.f);
        o.y = din * fmaxf(fmaf(din, a.y, bb.y), 0.f);
        o.z = din * fmaxf(fmaf(din, a.z, bb.z), 0.f);
        o.w = din * fmaxf(fmaf(din, a.w, bb.w), 0.f);
        g_p2[node * 4 + c] = o;
    }
}

// ---------------------------------------------------------------------------
// 4) Fused layer-2 aggregation + GEMM (@W2 + b2 + relu) + global mean pool.
//    Last consumer of g_cur -> zeroes it for the next graph replay.
// ---------------------------------------------------------------------------
__global__ __launch_bounds__(256) void k_agg2pool(const int* __restrict__ batch,
                                                  const float* __restrict__ W2,
                                                  const float* __restrict__ b2,
                                                  int n) {
    __shared__ float W2s[512];
    __shared__ float sp[8][32];
    __shared__ int   sg[8];

    int tid  = threadIdx.x;
    int lane = tid & 31;
    int w    = tid >> 5;
    int node = blockIdx.x * 8 + w;

    #pragma unroll
    for (int i = tid; i < 512; i += 256) W2s[i] = W2[i];

    float out = 0.f;
    int gid = -1;

    if (node < n) {
        int cnt = g_cur[node];
        float4 a = agg_warp(g_p2, node, lane, cnt);
        if (lane == 0) g_cur[node] = 0;   // self-clean for next replay
        float4 self = g_p2[node * 4 + (lane & 3)];
        a.x += self.x; a.y += self.y; a.z += self.z; a.w += self.w;
        float din = g_dinv[node];
        a.x *= din; a.y *= din; a.z *= din; a.w *= din;

        gid = __ldg(&batch[node]);
        __syncthreads();   // W2s ready
        float acc = __ldg(&b2[lane]);
        #pragma unroll
        for (int k = 0; k < 16; k++) {
            float comp = ((k & 3) == 0) ? a.x : ((k & 3) == 1) ? a.y
                       : ((k & 3) == 2) ? a.z : a.w;
            float v = __shfl_sync(0xffffffffu, comp, k >> 2);
            acc = fmaf(v, W2s[k * 32 + lane], acc);
        }
        out = fmaxf(acc, 0.f);
    } else {
        __syncthreads();   // matching barrier
    }

    sp[w][lane] = out;
    if (lane == 0) sg[w] = gid;
    __syncthreads();

    if (w == 0) {
        int cur = -1; float rs = 0.f, rc = 0.f;
        #pragma unroll
        for (int r = 0; r < 8; r++) {
            int g = sg[r];
            if (g < 0) continue;
            if (g != cur) {
                if (cur >= 0) {
                    atomicAdd(&g_pool[cur * 32 + lane], rs);
                    if (lane == 0) atomicAdd(&g_cnt[cur], rc);
                }
                cur = g; rs = 0.f; rc = 0.f;
            }
            rs += sp[r][lane];
            rc += 1.f;
        }
        if (cur >= 0) {
            atomicAdd(&g_pool[cur * 32 + lane], rs);
            if (lane == 0) atomicAdd(&g_cnt[cur], rc);
        }
    }
}

// ---------------------------------------------------------------------------
// 5) MLP head. Last consumer of g_pool/g_cnt/g_spn -> zeroes them.
// ---------------------------------------------------------------------------
__global__ __launch_bounds__(64) void k_mlp(const float* __restrict__ Wf1,
                                            const float* __restrict__ bf1,
                                            const float* __restrict__ Wf2,
                                            const float* __restrict__ bf2,
                                            float* __restrict__ out) {
    int g = threadIdx.x;
    if (g >= N_GRAPHS) return;

    float inv = 1.0f / fmaxf(g_cnt[g], 1.0f);
    float gv[32];
    #pragma unroll
    for (int c = 0; c < 32; c++) {
        gv[c] = g_pool[g * 32 + c] * inv;
        g_pool[g * 32 + c] = 0.0f;        // self-clean
    }
    g_cnt[g] = 0.0f;                      // self-clean
    if (g == 0) g_spn = 0;                // self-clean

    float h[64];
    #pragma unroll 8
    for (int j = 0; j < 64; j++) {
        float s = __ldg(&bf1[j]);
        #pragma unroll
        for (int c = 0; c < 32; c++) s = fmaf(gv[c], __ldg(&Wf1[c * 64 + j]), s);
        h[j] = fmaxf(s, 0.f);
    }

    #pragma unroll
    for (int o = 0; o < 8; o++) {
        float s = __ldg(&bf2[o]);
        #pragma unroll 16
        for (int j = 0; j < 64; j++) s = fmaf(h[j], __ldg(&Wf2[j * 8 + o]), s);
        out[g * 8 + o] = s;
    }
}

// ---------------------------------------------------------------------------
// Launch: 5 kernels (init eliminated via self-cleaning state).
// k_agg2pool at slot 4 -> profiled next round.
// ---------------------------------------------------------------------------
extern "C" void kernel_launch(void* const* d_in, const int* in_sizes, int n_in,
                              void* d_out, int out_size) {
    const float* x     = (const float*)d_in[0];
    const int*   ei    = (const int*)  d_in[1];
    const int*   batch = (const int*)  d_in[2];
    const float* W1    = (const float*)d_in[3];
    const float* b1    = (const float*)d_in[4];
    const float* W2    = (const float*)d_in[5];
    const float* b2    = (const float*)d_in[6];
    const float* Wf1   = (const float*)d_in[7];
    const float* bf1   = (const float*)d_in[8];
    const float* Wf2   = (const float*)d_in[9];
    const float* bf2   = (const float*)d_in[10];
    float* out = (float*)d_out;

    int N = in_sizes[0] / 128;
    int E = in_sizes[1] / 2;
    const int* src = ei;
    const int* dst = ei + E;

    bool v4ok = ((E & 3) == 0) &&
                ((((unsigned long long)src) & 15ull) == 0) &&
                ((((unsigned long long)dst) & 15ull) == 0);
    int E4 = v4ok ? (E >> 2) : 0;

    int gemmBlocks = CDIV(N, 128);

    if (v4ok) {
        int placeBlocks = CDIV(E4, 256);
        k_fused<<<gemmBlocks + placeBlocks, 256>>>(x, W1,
                (const int4*)src, (const int4*)dst, E4, N, gemmBlocks); // 1
    } else {
        k_gemm1_only<<<gemmBlocks, 256>>>(x, W1, N);
        k_place_tail<<<CDIV(E, 256), 256>>>(src, dst, 0, E);
    }
    k_scale<<<CDIV(N * 4, 256), 256>>>(N);                          // 2
    k_agg1 <<<CDIV(N, 8), 256>>>(b1, N);                            // 3
    k_agg2pool<<<CDIV(N, 8), 256>>>(batch, W2, b2, N);              // 4 <- profiled
    k_mlp  <<<1, 64>>>(Wf1, bf1, Wf2, bf2, out);                    // 5
}